// round 15
// baseline (speedup 1.0000x reference)
#include <cuda_runtime.h>
#include <cstdint>

#define B_   8
#define NQ_  64
#define N_   257
#define D_   768
#define H_   6
#define R_   64
#define DH_  128
#define MID_ 4096
#define BN_ROWS 2056
#define BQ_ROWS 512
#define NKT32 (D_ / 32)       // 24 tf32 k-tiles
#define SIMP  384              // padded sim row stride

// fused-GEMM job map: k (24it) | q (24it) | mid split-K2 (12it, atomic)
#define K_JOBS    102          // 17 x 6
#define Q_JOBS    24           // 4 x 6
#define MID_JOBS  1088         // 544 tiles x 2 k-halves
#define Q_JOB0    K_JOBS
#define MID_JOB0  (K_JOBS + Q_JOBS)
#define TOT_JOBS  (MID_JOB0 + MID_JOBS)   // 1214

// pre-round segment sizes (float4 units): x | ctx | Wq | Wk | Wv1 | Wout
#define X4    (BQ_ROWS * D_ / 4)
#define CTX4  (BN_ROWS * D_ / 4)
#define W4    (D_ * D_ / 4)
#define WV14  (MID_ * D_ / 4)
#define TOT4  (X4 + CTX4 + 3 * W4 + WV14)
#define MIDZ4 (BN_ROWS * MID_ / 4)         // g_mid zero span (float4)

// ---------------- scratch (device globals; no allocation allowed) ----------
__device__ __align__(256) float g_rnd[(size_t)TOT4 * 4];   // tf32-rounded inputs
__device__ float g_q[BQ_ROWS * (size_t)D_];                // tf32-rounded
__device__ float g_k[BN_ROWS * (size_t)D_];                // tf32-rounded
__device__ float g_mid[BN_ROWS * (size_t)MID_];            // raw (pre-LN), atomic-accum
__device__ float g_stats[BN_ROWS * 2];                     // mu, inv per row
__device__ float g_sim[(size_t)B_ * H_ * NQ_ * SIMP];      // raw logits (padded)
__device__ float g_w[(size_t)B_ * H_ * NQ_ * R_];
__device__ float g_outpre[BQ_ROWS * (size_t)D_];           // tf32-rounded
__device__ float g_part[4 * BQ_ROWS * (size_t)D_];         // out-GEMM partials

// ---------------------------- PTX helpers ----------------------------------
__device__ __forceinline__ unsigned smem_u32(const void* p) {
    return (unsigned)__cvta_generic_to_shared(p);
}
#define CPA16(dst_u32, src_ptr) \
    asm volatile("cp.async.cg.shared.global [%0], [%1], 16;\n" :: "r"(dst_u32), "l"(src_ptr))
#define LDSM_X4(r0, r1, r2, r3, addr) \
    asm volatile("ldmatrix.sync.aligned.m8n8.x4.shared.b16 {%0,%1,%2,%3}, [%4];" \
                 : "=r"(r0), "=r"(r1), "=r"(r2), "=r"(r3) : "r"(addr))
#define MMA1688_TF32(acc, a, b) \
    asm volatile( \
        "mma.sync.aligned.m16n8k8.row.col.f32.tf32.tf32.f32 " \
        "{%0,%1,%2,%3}, {%4,%5,%6,%7}, {%8,%9}, {%0,%1,%2,%3};\n" \
        : "+f"((acc)[0]), "+f"((acc)[1]), "+f"((acc)[2]), "+f"((acc)[3]) \
        : "r"((a)[0]), "r"((a)[1]), "r"((a)[2]), "r"((a)[3]), \
          "r"((b)[0]), "r"((b)[1]))

__device__ __forceinline__ uint32_t sw128(uint32_t off) {
    return off ^ ((off >> 3) & 0x70);
}
__device__ __forceinline__ float rna_tf32(float v) {
    uint32_t t;
    asm("cvt.rna.tf32.f32 %0, %1;" : "=r"(t) : "f"(v));
    return __uint_as_float(t);
}

// ---------------------------------------------------------------------------
// Pre-round all tf32-GEMM inputs (RNA) into g_rnd AND zero g_mid (atomic dst).
// ---------------------------------------------------------------------------
__global__ void round_tf32_kernel(const float* __restrict__ x,
                                  const float* __restrict__ ctx,
                                  const float* __restrict__ Wq,
                                  const float* __restrict__ Wk,
                                  const float* __restrict__ Wv1,
                                  const float* __restrict__ Wout,
                                  float* __restrict__ Y,
                                  float* __restrict__ midz) {
    const int i = blockIdx.x * 256 + threadIdx.x;
    if (i >= TOT4 + MIDZ4) return;
    if (i >= TOT4) {
        ((float4*)midz)[i - TOT4] = make_float4(0.f, 0.f, 0.f, 0.f);
        return;
    }
    int j = i;
    const float4* src;
    if (j < X4)                  src = (const float4*)x;
    else if ((j -= X4) < CTX4)   src = (const float4*)ctx;
    else if ((j -= CTX4) < W4)   src = (const float4*)Wq;
    else if ((j -= W4) < W4)     src = (const float4*)Wk;
    else if ((j -= W4) < WV14)   src = (const float4*)Wv1;
    else { j -= WV14;            src = (const float4*)Wout; }
    float4 v = src[j];
    v.x = rna_tf32(v.x); v.y = rna_tf32(v.y);
    v.z = rna_tf32(v.z); v.w = rna_tf32(v.w);
    ((float4*)Y)[i] = v;
}

// ---------------------------------------------------------------------------
// TF32 GEMM body, 128x128 tile. mode: 0=store, 1=store RNA-rounded,
// 2=atomicAdd (exactly-2-way split-K => commutative => deterministic).
// ---------------------------------------------------------------------------
#define STG_BYTES 32768

__device__ __forceinline__
void gemm_body_tf32(const float* __restrict__ A, int lda,
                    const float* __restrict__ Bm, int ldb, int NrowsB,
                    float* __restrict__ C, int M, int Ncols,
                    int nkt, int kt0, int mt, int nt, int mode, char* dyn) {
    const uint32_t base = smem_u32(dyn);

    const int tid = threadIdx.x;
    const int warp = tid >> 5, lane = tid & 31;
    const int wm = warp & 3, wn = warp >> 2;
    const int gr = lane >> 2, tig = lane & 3;
    const int lrow = lane & 7, lmat = lane >> 3;
    const int m0 = mt * 128, n0 = nt * 128;

    float acc[2][8][4];
#pragma unroll
    for (int mi = 0; mi < 2; mi++)
#pragma unroll
        for (int ni = 0; ni < 8; ni++)
#pragma unroll
            for (int j = 0; j < 4; j++) acc[mi][ni][j] = 0.f;

    auto load_stage = [&](int kt) {
        const uint32_t sb = base + (kt % 3) * STG_BYTES;
        const int k0 = (kt0 + kt) * 32;
#pragma unroll
        for (int i = 0; i < 4; i++) {
            const int c = tid + i * 256;
            const int row = c >> 3, c16 = c & 7;
            int grow = m0 + row; if (grow >= M) grow = M - 1;
            CPA16(sb + sw128((uint32_t)(row * 128 + c16 * 16)),
                  A + (size_t)grow * lda + k0 + c16 * 4);
        }
#pragma unroll
        for (int i = 0; i < 4; i++) {
            const int c = tid + i * 256;
            const int row = c >> 3, c16 = c & 7;
            int gn = n0 + row; if (gn >= NrowsB) gn = NrowsB - 1;
            CPA16(sb + 16384 + sw128((uint32_t)(row * 128 + c16 * 16)),
                  Bm + (size_t)gn * ldb + k0 + c16 * 4);
        }
        asm volatile("cp.async.commit_group;\n" ::);
    };

    load_stage(0);
    load_stage(1);

    for (int kt = 0; kt < nkt; kt++) {
        const int s = kt % 3;
        asm volatile("cp.async.wait_group 1;\n" ::);
        __syncthreads();
        if (kt + 2 < nkt) load_stage(kt + 2);
        else asm volatile("cp.async.commit_group;\n" ::);

        const uint32_t sA = base + s * STG_BYTES;
        const uint32_t sB = sA + 16384;
#pragma unroll
        for (int kk = 0; kk < 4; kk++) {
            const int kb = kk * 32;
            uint32_t a[2][4], b[8][2];
#pragma unroll
            for (int mi = 0; mi < 2; mi++) {
                const int r = wm * 32 + mi * 16 + ((lmat & 1) << 3) + lrow;
                LDSM_X4(a[mi][0], a[mi][1], a[mi][2], a[mi][3],
                        sA + sw128((uint32_t)(r * 128 + kb + ((lmat >> 1) << 4))));
            }
#pragma unroll
            for (int gp = 0; gp < 4; gp++) {
                const int n = wn * 64 + gp * 16 + ((lmat >> 1) << 3) + lrow;
                LDSM_X4(b[2 * gp][0], b[2 * gp][1], b[2 * gp + 1][0], b[2 * gp + 1][1],
                        sB + sw128((uint32_t)(n * 128 + kb + ((lmat & 1) << 4))));
            }
#pragma unroll
            for (int mi = 0; mi < 2; mi++)
#pragma unroll
                for (int ni = 0; ni < 8; ni++)
                    MMA1688_TF32(acc[mi][ni], a[mi], b[ni]);
        }
    }

#pragma unroll
    for (int mi = 0; mi < 2; mi++)
#pragma unroll
        for (int ni = 0; ni < 8; ni++) {
            const int c = n0 + wn * 64 + ni * 8 + 2 * tig;
            int r = m0 + wm * 32 + mi * 16 + gr;
            if (mode == 2) {
                if (r < M) {
                    atomicAdd(&C[(size_t)r * Ncols + c],     acc[mi][ni][0]);
                    atomicAdd(&C[(size_t)r * Ncols + c + 1], acc[mi][ni][1]);
                }
                r += 8;
                if (r < M) {
                    atomicAdd(&C[(size_t)r * Ncols + c],     acc[mi][ni][2]);
                    atomicAdd(&C[(size_t)r * Ncols + c + 1], acc[mi][ni][3]);
                }
            } else {
                float2 v0 = make_float2(acc[mi][ni][0], acc[mi][ni][1]);
                float2 v1 = make_float2(acc[mi][ni][2], acc[mi][ni][3]);
                if (mode == 1) {
                    v0.x = rna_tf32(v0.x); v0.y = rna_tf32(v0.y);
                    v1.x = rna_tf32(v1.x); v1.y = rna_tf32(v1.y);
                }
                if (r < M) *(float2*)&C[(size_t)r * Ncols + c] = v0;
                r += 8;
                if (r < M) *(float2*)&C[(size_t)r * Ncols + c] = v1;
            }
        }
}

// Fused tf32 launch: k + q (24-iter, first = LPT) then mid split-K2 (12-iter,
// atomicAdd into zeroed g_mid).
__global__ __launch_bounds__(256, 2)
void gemm_fused_tf32(const float* __restrict__ ctx,
                     const float* __restrict__ Wv1, float* __restrict__ midp,
                     const float* __restrict__ Wk,  float* __restrict__ kp,
                     const float* __restrict__ x,
                     const float* __restrict__ Wq,  float* __restrict__ qp) {
    extern __shared__ char dyn[];
    const int bid = blockIdx.x;
    if (bid < K_JOBS) {
        gemm_body_tf32(ctx, D_, Wk, D_, D_, kp, BN_ROWS, D_,
                       NKT32, 0, bid / 6, bid % 6, 1, dyn);
    } else if (bid < MID_JOB0) {
        const int t = bid - Q_JOB0;
        gemm_body_tf32(x, D_, Wq, D_, D_, qp, BQ_ROWS, D_,
                       NKT32, 0, t / 6, t % 6, 1, dyn);
    } else {
        const int t = bid - MID_JOB0;
        const int tile = t >> 1, z = t & 1;
        gemm_body_tf32(ctx, D_, Wv1, D_, MID_, midp, BN_ROWS, MID_,
                       NKT32 / 2, z * (NKT32 / 2), tile / 32, tile % 32, 2, dyn);
    }
}

// sim GEMM: per (b,h): sim[64,257] = q_bh[64,128] @ k_bh[257,128]^T.
__global__ __launch_bounds__(256, 2)
void gemm_sim_tf32(const float* __restrict__ qp, const float* __restrict__ kp,
                   float* __restrict__ simp) {
    extern __shared__ char dyn[];
    const int bh = blockIdx.y;
    const int b = bh / H_, h = bh % H_;
    gemm_body_tf32(qp + (size_t)b * NQ_ * D_ + h * DH_, D_,
                   kp + (size_t)b * N_ * D_ + h * DH_, D_, N_,
                   simp + (size_t)bh * NQ_ * SIMP, NQ_, SIMP,
                   DH_ / 32, 0, 0, blockIdx.x, 0, dyn);
}

// Out GEMM: outpre(tf32-rounded) @ Wout_r^T, split-K=4 via blockIdx.z.
__global__ __launch_bounds__(256, 2)
void gemm_out_tf32(const float* __restrict__ A, const float* __restrict__ Bm,
                   float* __restrict__ C) {
    extern __shared__ char dyn[];
    gemm_body_tf32(A, D_, Bm, D_, D_, C + (size_t)blockIdx.z * BQ_ROWS * D_,
                   BQ_ROWS, D_, NKT32 / 4, blockIdx.z * (NKT32 / 4),
                   blockIdx.y, blockIdx.x, 0, dyn);
}

// ---------------------------------------------------------------------------
// LN stats only: mu, inv per row of mid (application deferred into attn_w2).
// ---------------------------------------------------------------------------
__global__ void ln_stats_kernel(const float* __restrict__ mid,
                                float* __restrict__ stats) {
    const int row = blockIdx.x;
    const float4* p = (const float4*)(mid + (size_t)row * MID_);
    const int tid = threadIdx.x;
    const int lane = tid & 31, warp = tid >> 5;

    float s = 0.f, ss = 0.f;
#pragma unroll
    for (int j = 0; j < 4; j++) {
        const float4 v = p[tid + (j << 8)];
        s  += v.x + v.y + v.z + v.w;
        ss += v.x * v.x + v.y * v.y + v.z * v.z + v.w * v.w;
    }
#pragma unroll
    for (int off = 16; off; off >>= 1) {
        s  += __shfl_xor_sync(~0u, s,  off);
        ss += __shfl_xor_sync(~0u, ss, off);
    }
    __shared__ float rs[8], rss[8];
    if (lane == 0) { rs[warp] = s; rss[warp] = ss; }
    __syncthreads();
    if (tid == 0) {
        s = 0.f; ss = 0.f;
#pragma unroll
        for (int k = 0; k < 8; k++) { s += rs[k]; ss += rss[k]; }
        const float mu  = s * (1.f / MID_);
        const float var = ss * (1.f / MID_) - mu * mu;
        stats[row * 2]     = mu;
        stats[row * 2 + 1] = rsqrtf(var + 1e-5f);
    }
}

// ---------------------------------------------------------------------------
// Attention stage 2 with inline softmax AND LayerNorm (Σa=1 algebra):
//   warps 0..5: softmax row h over sim logits, store a'[h,n]=a·inv[n] to smem
//   S2[h] = Σ a'·mu;  w[h,r] = g[c]·(Σ a'·mid_raw[n,c] − S2[h]) + bt[c]
// Block per (i, b); 384 threads = 6h x 64r; mid slice read ONCE for all h.
// ---------------------------------------------------------------------------
__global__ __launch_bounds__(384)
void attn_w2_kernel(const float* __restrict__ simp,
                    const float* __restrict__ mid,
                    const float* __restrict__ stats,
                    const float* __restrict__ ln_g,
                    const float* __restrict__ ln_b,
                    float* __restrict__ w) {
    const int i = blockIdx.x, b = blockIdx.y;
    const int tid = threadIdx.x;
    const int h = tid / 64, r = tid & 63;
    const int warp = tid >> 5, lane = tid & 31;

    __shared__ float ats[H_ * N_];     // a' = softmax(a) * inv_ln[n]
    __shared__ float muv[N_];
    __shared__ float s2p[H_][64];
    __shared__ float s2[H_];

    for (int n = tid; n < N_; n += 384)
        muv[n] = stats[(b * N_ + n) * 2];

    // softmax for head hh = warp (warps 0..5)
    if (warp < H_) {
        const int hh = warp;
        const float* src = simp + ((size_t)(b * H_ + hh) * NQ_ + i) * SIMP;
        const float sc = 0.08838834764831844f;   // dh^-0.5
        float vals[9];
        float m = -1e30f;
#pragma unroll
        for (int j = 0; j < 9; j++) {
            const int n = lane + j * 32;
            vals[j] = (n < N_) ? src[n] * sc : -1e30f;
            m = fmaxf(m, vals[j]);
        }
#pragma unroll
        for (int off = 16; off; off >>= 1) m = fmaxf(m, __shfl_xor_sync(~0u, m, off));
        float s = 0.f;
#pragma unroll
        for (int j = 0; j < 9; j++) {
            vals[j] = __expf(vals[j] - m);
            s += vals[j];
        }
#pragma unroll
        for (int off = 16; off; off >>= 1) s += __shfl_xor_sync(~0u, s, off);
        const float inv = 1.f / s;
#pragma unroll
        for (int j = 0; j < 9; j++) {
            const int n = lane + j * 32;
            if (n < N_)
                ats[hh * N_ + n] = vals[j] * inv * stats[(b * N_ + n) * 2 + 1];
        }
    }
    __syncthreads();

    // S2[h] = sum_n a'[h,n] * mu[n]
    {
        float p = 0.f;
        for (int n = r; n < N_; n += 64) p += ats[h * N_ + n] * muv[n];
        s2p[h][r] = p;
    }
    __syncthreads();
    if (r == 0) {
        float t = 0.f;
#pragma unroll
        for (int j = 0; j < 64; j++) t += s2p[h][j];
        s2[h] = t;
    }
    __syncthreads();

    const int c = i * R_ + r;
    const float* mp = mid + (size_t)b * N_ * MID_ + c;
    float acc = 0.f;
#pragma unroll 4
    for (int n = 0; n < N_; n++)
        acc += ats[h * N_ + n] * mp[(size_t)n * MID_];
    w[(((size_t)b * H_ + h) * NQ_ + i) * R_ + r] =
        ln_g[c] * (acc - s2[h]) + ln_b[c];
}

// ---------------------------------------------------------------------------
// Rank expansion: outpre[b,i,d] = sum_r Wconv[i,d,r] * w[b, d/128, i, r].
// Output stored tf32-rounded (feeds tf32 out-GEMM directly).
// ---------------------------------------------------------------------------
__global__ void convout_kernel(const float* __restrict__ w,
                               const float* __restrict__ Wconv,
                               float* __restrict__ outpre) {
    const int i = blockIdx.x % NQ_;
    const int b = blockIdx.x / NQ_;
    const int tid = threadIdx.x;

    __shared__ float ws[H_ * R_];
    for (int j = tid; j < H_ * R_; j += 256)
        ws[j] = w[(((size_t)b * H_ + (j >> 6)) * NQ_ + i) * R_ + (j & 63)];
    __syncthreads();

    for (int d = tid; d < D_; d += 256) {
        const float* wc = Wconv + ((size_t)i * D_ + d) * R_;
        const float* wv = &ws[(d >> 7) * R_];
        float acc = 0.f;
#pragma unroll
        for (int r = 0; r < R_; r += 4) {
            const float4 c4 = *(const float4*)&wc[r];
            acc += c4.x * wv[r] + c4.y * wv[r + 1] + c4.z * wv[r + 2] + c4.w * wv[r + 3];
        }
        outpre[((size_t)b * NQ_ + i) * D_ + d] = rna_tf32(acc);
    }
}

// ---------------------------------------------------------------------------
// Split-K reduction (out-GEMM only).
// ---------------------------------------------------------------------------
template <int KSPL>
__global__ void reduce_k(const float* __restrict__ P, float* __restrict__ C,
                         int elems4) {
    const int i = blockIdx.x * 256 + threadIdx.x;
    if (i >= elems4) return;
    const float4* p = (const float4*)P;
    float4 v = p[i];
#pragma unroll
    for (int z = 1; z < KSPL; z++) {
        const float4 u = p[(size_t)z * elems4 + i];
        v.x += u.x; v.y += u.y; v.z += u.z; v.w += u.w;
    }
    ((float4*)C)[i] = v;
}

// ---------------------------------------------------------------------------
extern "C" void kernel_launch(void* const* d_in, const int* in_sizes, int n_in,
                              void* d_out, int out_size) {
    const float* x     = (const float*)d_in[0];
    const float* ctx   = (const float*)d_in[1];
    const float* Wq    = (const float*)d_in[2];
    const float* Wk    = (const float*)d_in[3];
    const float* Wv1   = (const float*)d_in[4];
    const float* ln_g  = (const float*)d_in[5];
    const float* ln_b  = (const float*)d_in[6];
    const float* Wconv = (const float*)d_in[7];
    const float* Wout  = (const float*)d_in[8];
    float* out = (float*)d_out;

    float *qp, *kp, *midp, *st, *simp, *wp, *opp, *pp, *rnd;
    cudaGetSymbolAddress((void**)&qp,   g_q);
    cudaGetSymbolAddress((void**)&kp,   g_k);
    cudaGetSymbolAddress((void**)&midp, g_mid);
    cudaGetSymbolAddress((void**)&st,   g_stats);
    cudaGetSymbolAddress((void**)&simp, g_sim);
    cudaGetSymbolAddress((void**)&wp,   g_w);
    cudaGetSymbolAddress((void**)&opp,  g_outpre);
    cudaGetSymbolAddress((void**)&pp,   g_part);
    cudaGetSymbolAddress((void**)&rnd,  g_rnd);
    float* x_r    = rnd;
    float* ctx_r  = x_r + (size_t)X4 * 4;
    float* Wq_r   = ctx_r + (size_t)CTX4 * 4;
    float* Wk_r   = Wq_r + (size_t)W4 * 4;
    float* Wv1_r  = Wk_r + (size_t)W4 * 4;
    float* Wout_r = Wv1_r + (size_t)WV14 * 4;

    const int SMEM = 3 * STG_BYTES;   // 98304
    cudaFuncSetAttribute(gemm_fused_tf32, cudaFuncAttributeMaxDynamicSharedMemorySize, SMEM);
    cudaFuncSetAttribute(gemm_sim_tf32,   cudaFuncAttributeMaxDynamicSharedMemorySize, SMEM);
    cudaFuncSetAttribute(gemm_out_tf32,   cudaFuncAttributeMaxDynamicSharedMemorySize, SMEM);

    const int T = 256;
    auto blks = [](int n) { return (n + 255) / 256; };

    // pre-round all tf32-GEMM inputs (RNA) + zero g_mid (atomic destination)
    round_tf32_kernel<<<blks(TOT4 + MIDZ4), T>>>(x, ctx, Wq, Wk, Wv1, Wout,
                                                 rnd, midp);

    // ONE tf32 launch: k + q (long jobs first) + mid split-K2 atomic
    gemm_fused_tf32<<<TOT_JOBS, T, SMEM>>>(ctx_r, Wv1_r, midp, Wk_r, kp,
                                           x_r, Wq_r, qp);

    // LN stats (application deferred into attn_w2)
    ln_stats_kernel<<<BN_ROWS, 256>>>(midp, st);

    // attention: sim as batched tf32 GEMM; softmax folded into attn_w2
    gemm_sim_tf32<<<dim3(3, B_ * H_), T, SMEM>>>(qp, kp, simp);
    attn_w2_kernel<<<dim3(NQ_, B_), 384>>>(simp, midp, st, ln_g, ln_b, wp);

    convout_kernel<<<BQ_ROWS, 256>>>(wp, Wconv, opp);

    // final = outpre @ Wout^T, tf32, split-K=4
    gemm_out_tf32<<<dim3(D_ / 128, BQ_ROWS / 128, 4), T, SMEM>>>(opp, Wout_r, pp);
    reduce_k<4><<<blks(BQ_ROWS * D_ / 4), T>>>(pp, out, BQ_ROWS * D_ / 4);
}

// round 16
// speedup vs baseline: 1.0453x; 1.0453x over previous
#include <cuda_runtime.h>
#include <cstdint>

#define B_   8
#define NQ_  64
#define N_   257
#define D_   768
#define H_   6
#define R_   64
#define DH_  128
#define MID_ 4096
#define BN_ROWS 2056
#define BQ_ROWS 512
#define NKT32 (D_ / 32)       // 24 tf32 k-tiles
#define SIMP  384              // padded sim row stride

// fused-GEMM job map (R14 schedule): mid | k | q, all 24-iter CTAs
#define MID_TILES 544          // 17 m-tiles x 32 n-tiles
#define K_B0      544          // k: 17 x 6 = 102
#define Q_B0      646          // q: 4 x 6 = 24
#define TOT_TILES 670

// merged sim+lnstats grid
#define SIM_CTAS  (3 * B_ * H_)            // 144
#define SIMLN_CTAS (SIM_CTAS + BN_ROWS)    // 2200

// pre-round segment sizes (float4 units): x | ctx | Wq | Wk | Wv1 | Wout
#define X4    (BQ_ROWS * D_ / 4)
#define CTX4  (BN_ROWS * D_ / 4)
#define W4    (D_ * D_ / 4)
#define WV14  (MID_ * D_ / 4)
#define TOT4  (X4 + CTX4 + 3 * W4 + WV14)

// ---------------- scratch (device globals; no allocation allowed) ----------
__device__ __align__(256) float g_rnd[(size_t)TOT4 * 4];   // tf32-rounded inputs
__device__ float g_q[BQ_ROWS * (size_t)D_];                // tf32-rounded
__device__ float g_k[BN_ROWS * (size_t)D_];                // tf32-rounded
__device__ float g_mid[BN_ROWS * (size_t)MID_];            // raw (pre-LN)
__device__ float g_stats[BN_ROWS * 2];                     // mu, inv per row
__device__ float g_sim[(size_t)B_ * H_ * NQ_ * SIMP];      // raw logits (padded)
__device__ float g_w[(size_t)B_ * H_ * NQ_ * R_];
__device__ float g_outpre[BQ_ROWS * (size_t)D_];           // tf32-rounded
__device__ float g_part[4 * BQ_ROWS * (size_t)D_];         // out-GEMM partials

// ---------------------------- PTX helpers ----------------------------------
__device__ __forceinline__ unsigned smem_u32(const void* p) {
    return (unsigned)__cvta_generic_to_shared(p);
}
#define CPA16(dst_u32, src_ptr) \
    asm volatile("cp.async.cg.shared.global [%0], [%1], 16;\n" :: "r"(dst_u32), "l"(src_ptr))
#define LDSM_X4(r0, r1, r2, r3, addr) \
    asm volatile("ldmatrix.sync.aligned.m8n8.x4.shared.b16 {%0,%1,%2,%3}, [%4];" \
                 : "=r"(r0), "=r"(r1), "=r"(r2), "=r"(r3) : "r"(addr))
#define MMA1688_TF32(acc, a, b) \
    asm volatile( \
        "mma.sync.aligned.m16n8k8.row.col.f32.tf32.tf32.f32 " \
        "{%0,%1,%2,%3}, {%4,%5,%6,%7}, {%8,%9}, {%0,%1,%2,%3};\n" \
        : "+f"((acc)[0]), "+f"((acc)[1]), "+f"((acc)[2]), "+f"((acc)[3]) \
        : "r"((a)[0]), "r"((a)[1]), "r"((a)[2]), "r"((a)[3]), \
          "r"((b)[0]), "r"((b)[1]))

__device__ __forceinline__ uint32_t sw128(uint32_t off) {
    return off ^ ((off >> 3) & 0x70);
}
__device__ __forceinline__ float rna_tf32(float v) {
    uint32_t t;
    asm("cvt.rna.tf32.f32 %0, %1;" : "=r"(t) : "f"(v));
    return __uint_as_float(t);
}

// ---------------------------------------------------------------------------
// Pre-round all tf32-GEMM inputs to tf32 (RNA) into g_rnd (one flat pass).
// ---------------------------------------------------------------------------
__global__ void round_tf32_kernel(const float* __restrict__ x,
                                  const float* __restrict__ ctx,
                                  const float* __restrict__ Wq,
                                  const float* __restrict__ Wk,
                                  const float* __restrict__ Wv1,
                                  const float* __restrict__ Wout,
                                  float* __restrict__ Y) {
    const int i = blockIdx.x * 256 + threadIdx.x;
    if (i >= TOT4) return;
    int j = i;
    const float4* src;
    if (j < X4)                  src = (const float4*)x;
    else if ((j -= X4) < CTX4)   src = (const float4*)ctx;
    else if ((j -= CTX4) < W4)   src = (const float4*)Wq;
    else if ((j -= W4) < W4)     src = (const float4*)Wk;
    else if ((j -= W4) < WV14)   src = (const float4*)Wv1;
    else { j -= WV14;            src = (const float4*)Wout; }
    float4 v = src[j];
    v.x = rna_tf32(v.x); v.y = rna_tf32(v.y);
    v.z = rna_tf32(v.z); v.w = rna_tf32(v.w);
    ((float4*)Y)[i] = v;
}

// ---------------------------------------------------------------------------
// TF32 GEMM body, 128x128 tile (generalized: lda/ldb, B-row clamp, optional
// RNA-rounded output). Proven pipeline from R10-R14.
// ---------------------------------------------------------------------------
#define STG_BYTES 32768

__device__ __forceinline__
void gemm_body_tf32(const float* __restrict__ A, int lda,
                    const float* __restrict__ Bm, int ldb, int NrowsB,
                    float* __restrict__ C, int M, int Ncols,
                    int nkt, int kt0, int mt, int nt, int roundC, char* dyn) {
    const uint32_t base = smem_u32(dyn);

    const int tid = threadIdx.x;
    const int warp = tid >> 5, lane = tid & 31;
    const int wm = warp & 3, wn = warp >> 2;
    const int gr = lane >> 2, tig = lane & 3;
    const int lrow = lane & 7, lmat = lane >> 3;
    const int m0 = mt * 128, n0 = nt * 128;

    float acc[2][8][4];
#pragma unroll
    for (int mi = 0; mi < 2; mi++)
#pragma unroll
        for (int ni = 0; ni < 8; ni++)
#pragma unroll
            for (int j = 0; j < 4; j++) acc[mi][ni][j] = 0.f;

    auto load_stage = [&](int kt) {
        const uint32_t sb = base + (kt % 3) * STG_BYTES;
        const int k0 = (kt0 + kt) * 32;
#pragma unroll
        for (int i = 0; i < 4; i++) {
            const int c = tid + i * 256;
            const int row = c >> 3, c16 = c & 7;
            int grow = m0 + row; if (grow >= M) grow = M - 1;
            CPA16(sb + sw128((uint32_t)(row * 128 + c16 * 16)),
                  A + (size_t)grow * lda + k0 + c16 * 4);
        }
#pragma unroll
        for (int i = 0; i < 4; i++) {
            const int c = tid + i * 256;
            const int row = c >> 3, c16 = c & 7;
            int gn = n0 + row; if (gn >= NrowsB) gn = NrowsB - 1;
            CPA16(sb + 16384 + sw128((uint32_t)(row * 128 + c16 * 16)),
                  Bm + (size_t)gn * ldb + k0 + c16 * 4);
        }
        asm volatile("cp.async.commit_group;\n" ::);
    };

    load_stage(0);
    load_stage(1);

    for (int kt = 0; kt < nkt; kt++) {
        const int s = kt % 3;
        asm volatile("cp.async.wait_group 1;\n" ::);
        __syncthreads();
        if (kt + 2 < nkt) load_stage(kt + 2);
        else asm volatile("cp.async.commit_group;\n" ::);

        const uint32_t sA = base + s * STG_BYTES;
        const uint32_t sB = sA + 16384;
#pragma unroll
        for (int kk = 0; kk < 4; kk++) {
            const int kb = kk * 32;
            uint32_t a[2][4], b[8][2];
#pragma unroll
            for (int mi = 0; mi < 2; mi++) {
                const int r = wm * 32 + mi * 16 + ((lmat & 1) << 3) + lrow;
                LDSM_X4(a[mi][0], a[mi][1], a[mi][2], a[mi][3],
                        sA + sw128((uint32_t)(r * 128 + kb + ((lmat >> 1) << 4))));
            }
#pragma unroll
            for (int gp = 0; gp < 4; gp++) {
                const int n = wn * 64 + gp * 16 + ((lmat >> 1) << 3) + lrow;
                LDSM_X4(b[2 * gp][0], b[2 * gp][1], b[2 * gp + 1][0], b[2 * gp + 1][1],
                        sB + sw128((uint32_t)(n * 128 + kb + ((lmat & 1) << 4))));
            }
#pragma unroll
            for (int mi = 0; mi < 2; mi++)
#pragma unroll
                for (int ni = 0; ni < 8; ni++)
                    MMA1688_TF32(acc[mi][ni], a[mi], b[ni]);
        }
    }

#pragma unroll
    for (int mi = 0; mi < 2; mi++)
#pragma unroll
        for (int ni = 0; ni < 8; ni++) {
            const int c = n0 + wn * 64 + ni * 8 + 2 * tig;
            float2 v0 = make_float2(acc[mi][ni][0], acc[mi][ni][1]);
            float2 v1 = make_float2(acc[mi][ni][2], acc[mi][ni][3]);
            if (roundC) {
                v0.x = rna_tf32(v0.x); v0.y = rna_tf32(v0.y);
                v1.x = rna_tf32(v1.x); v1.y = rna_tf32(v1.y);
            }
            int r = m0 + wm * 32 + mi * 16 + gr;
            if (r < M) *(float2*)&C[(size_t)r * Ncols + c] = v0;
            r += 8;
            if (r < M) *(float2*)&C[(size_t)r * Ncols + c] = v1;
        }
}

// Fused tf32 launch: mid + k + q, one grid (q/k outputs RNA-rounded).
__global__ __launch_bounds__(256, 2)
void gemm_fused_tf32(const float* __restrict__ ctx,
                     const float* __restrict__ Wv1, float* __restrict__ midp,
                     const float* __restrict__ Wk,  float* __restrict__ kp,
                     const float* __restrict__ x,
                     const float* __restrict__ Wq,  float* __restrict__ qp) {
    extern __shared__ char dyn[];
    const int bid = blockIdx.x;
    if (bid < MID_TILES) {
        gemm_body_tf32(ctx, D_, Wv1, D_, MID_, midp, BN_ROWS, MID_,
                       NKT32, 0, bid / 32, bid % 32, 0, dyn);
    } else if (bid < Q_B0) {
        const int t = bid - K_B0;
        gemm_body_tf32(ctx, D_, Wk, D_, D_, kp, BN_ROWS, D_,
                       NKT32, 0, t / 6, t % 6, 1, dyn);
    } else {
        const int t = bid - Q_B0;
        gemm_body_tf32(x, D_, Wq, D_, D_, qp, BQ_ROWS, D_,
                       NKT32, 0, t / 6, t % 6, 1, dyn);
    }
}

// ---------------------------------------------------------------------------
// Merged launch: sim GEMM CTAs (144, long jobs first) + ln_stats CTAs (2056).
//  sim: per (b,h): sim[64,257] = q_bh[64,128] @ k_bh[257,128]^T
//  ln:  mu, inv per row of mid (application deferred into attn_w2)
// ---------------------------------------------------------------------------
__global__ __launch_bounds__(256, 2)
void sim_lnstats_kernel(const float* __restrict__ qp, const float* __restrict__ kp,
                        float* __restrict__ simp,
                        const float* __restrict__ mid, float* __restrict__ stats) {
    extern __shared__ char dyn[];
    const int bid = blockIdx.x;
    if (bid < SIM_CTAS) {
        const int bh = bid / 3, nt = bid % 3;
        const int b = bh / H_, h = bh % H_;
        gemm_body_tf32(qp + (size_t)b * NQ_ * D_ + h * DH_, D_,
                       kp + (size_t)b * N_ * D_ + h * DH_, D_, N_,
                       simp + (size_t)bh * NQ_ * SIMP, NQ_, SIMP,
                       DH_ / 32, 0, 0, nt, 0, dyn);
        return;
    }
    // ---- ln_stats body ----
    const int row = bid - SIM_CTAS;
    const float4* p = (const float4*)(mid + (size_t)row * MID_);
    const int tid = threadIdx.x;
    const int lane = tid & 31, warp = tid >> 5;

    float s = 0.f, ss = 0.f;
#pragma unroll
    for (int j = 0; j < 4; j++) {
        const float4 v = p[tid + (j << 8)];
        s  += v.x + v.y + v.z + v.w;
        ss += v.x * v.x + v.y * v.y + v.z * v.z + v.w * v.w;
    }
#pragma unroll
    for (int off = 16; off; off >>= 1) {
        s  += __shfl_xor_sync(~0u, s,  off);
        ss += __shfl_xor_sync(~0u, ss, off);
    }
    __shared__ float rs[8], rss[8];
    if (lane == 0) { rs[warp] = s; rss[warp] = ss; }
    __syncthreads();
    if (tid == 0) {
        s = 0.f; ss = 0.f;
#pragma unroll
        for (int k = 0; k < 8; k++) { s += rs[k]; ss += rss[k]; }
        const float mu  = s * (1.f / MID_);
        const float var = ss * (1.f / MID_) - mu * mu;
        stats[row * 2]     = mu;
        stats[row * 2 + 1] = rsqrtf(var + 1e-5f);
    }
}

// Out GEMM: outpre(tf32-rounded) @ Wout_r^T, split-K=4 via blockIdx.z.
__global__ __launch_bounds__(256, 2)
void gemm_out_tf32(const float* __restrict__ A, const float* __restrict__ Bm,
                   float* __restrict__ C) {
    extern __shared__ char dyn[];
    gemm_body_tf32(A, D_, Bm, D_, D_, C + (size_t)blockIdx.z * BQ_ROWS * D_,
                   BQ_ROWS, D_, NKT32 / 4, blockIdx.z * (NKT32 / 4),
                   blockIdx.y, blockIdx.x, 0, dyn);
}

// ---------------------------------------------------------------------------
// Attention stage 2 with inline softmax AND LayerNorm (Σa=1 algebra):
//   warps 0..5: softmax row h over sim logits, store a'[h,n]=a·inv_ln[n]
//   S2[h] = Σ a'·mu;  w[h,r] = g[c]·(Σ a'·mid_raw[n,c] − S2[h]) + bt[c]
// Block per (i, b); 384 threads = 6h x 64r; mid slice read ONCE for all h.
// ---------------------------------------------------------------------------
__global__ __launch_bounds__(384)
void attn_w2_kernel(const float* __restrict__ simp,
                    const float* __restrict__ mid,
                    const float* __restrict__ stats,
                    const float* __restrict__ ln_g,
                    const float* __restrict__ ln_b,
                    float* __restrict__ w) {
    const int i = blockIdx.x, b = blockIdx.y;
    const int tid = threadIdx.x;
    const int h = tid / 64, r = tid & 63;
    const int warp = tid >> 5, lane = tid & 31;

    __shared__ float ats[H_ * N_];     // a' = softmax(a) * inv_ln[n]
    __shared__ float muv[N_];
    __shared__ float s2p[H_][64];
    __shared__ float s2[H_];

    for (int n = tid; n < N_; n += 384)
        muv[n] = stats[(b * N_ + n) * 2];

    // softmax for head hh = warp (warps 0..5)
    if (warp < H_) {
        const int hh = warp;
        const float* src = simp + ((size_t)(b * H_ + hh) * NQ_ + i) * SIMP;
        const float sc = 0.08838834764831844f;   // dh^-0.5
        float vals[9];
        float m = -1e30f;
#pragma unroll
        for (int j = 0; j < 9; j++) {
            const int n = lane + j * 32;
            vals[j] = (n < N_) ? src[n] * sc : -1e30f;
            m = fmaxf(m, vals[j]);
        }
#pragma unroll
        for (int off = 16; off; off >>= 1) m = fmaxf(m, __shfl_xor_sync(~0u, m, off));
        float s = 0.f;
#pragma unroll
        for (int j = 0; j < 9; j++) {
            vals[j] = __expf(vals[j] - m);
            s += vals[j];
        }
#pragma unroll
        for (int off = 16; off; off >>= 1) s += __shfl_xor_sync(~0u, s, off);
        const float inv = 1.f / s;
#pragma unroll
        for (int j = 0; j < 9; j++) {
            const int n = lane + j * 32;
            if (n < N_)
                ats[hh * N_ + n] = vals[j] * inv * stats[(b * N_ + n) * 2 + 1];
        }
    }
    __syncthreads();

    // S2[h] = sum_n a'[h,n] * mu[n]
    {
        float p = 0.f;
        for (int n = r; n < N_; n += 64) p += ats[h * N_ + n] * muv[n];
        s2p[h][r] = p;
    }
    __syncthreads();
    if (r == 0) {
        float t = 0.f;
#pragma unroll
        for (int j = 0; j < 64; j++) t += s2p[h][j];
        s2[h] = t;
    }
    __syncthreads();

    const int c = i * R_ + r;
    const float* mp = mid + (size_t)b * N_ * MID_ + c;
    float acc = 0.f;
#pragma unroll 4
    for (int n = 0; n < N_; n++)
        acc += ats[h * N_ + n] * mp[(size_t)n * MID_];
    w[(((size_t)b * H_ + h) * NQ_ + i) * R_ + r] =
        ln_g[c] * (acc - s2[h]) + ln_b[c];
}

// ---------------------------------------------------------------------------
// Rank expansion: outpre[b,i,d] = sum_r Wconv[i,d,r] * w[b, d/128, i, r].
// Output stored tf32-rounded (feeds tf32 out-GEMM directly).
// ---------------------------------------------------------------------------
__global__ void convout_kernel(const float* __restrict__ w,
                               const float* __restrict__ Wconv,
                               float* __restrict__ outpre) {
    const int i = blockIdx.x % NQ_;
    const int b = blockIdx.x / NQ_;
    const int tid = threadIdx.x;

    __shared__ float ws[H_ * R_];
    for (int j = tid; j < H_ * R_; j += 256)
        ws[j] = w[(((size_t)b * H_ + (j >> 6)) * NQ_ + i) * R_ + (j & 63)];
    __syncthreads();

    for (int d = tid; d < D_; d += 256) {
        const float* wc = Wconv + ((size_t)i * D_ + d) * R_;
        const float* wv = &ws[(d >> 7) * R_];
        float acc = 0.f;
#pragma unroll
        for (int r = 0; r < R_; r += 4) {
            const float4 c4 = *(const float4*)&wc[r];
            acc += c4.x * wv[r] + c4.y * wv[r + 1] + c4.z * wv[r + 2] + c4.w * wv[r + 3];
        }
        outpre[((size_t)b * NQ_ + i) * D_ + d] = rna_tf32(acc);
    }
}

// ---------------------------------------------------------------------------
// Split-K reduction (out-GEMM only).
// ---------------------------------------------------------------------------
template <int KSPL>
__global__ void reduce_k(const float* __restrict__ P, float* __restrict__ C,
                         int elems4) {
    const int i = blockIdx.x * 256 + threadIdx.x;
    if (i >= elems4) return;
    const float4* p = (const float4*)P;
    float4 v = p[i];
#pragma unroll
    for (int z = 1; z < KSPL; z++) {
        const float4 u = p[(size_t)z * elems4 + i];
        v.x += u.x; v.y += u.y; v.z += u.z; v.w += u.w;
    }
    ((float4*)C)[i] = v;
}

// ---------------------------------------------------------------------------
extern "C" void kernel_launch(void* const* d_in, const int* in_sizes, int n_in,
                              void* d_out, int out_size) {
    const float* x     = (const float*)d_in[0];
    const float* ctx   = (const float*)d_in[1];
    const float* Wq    = (const float*)d_in[2];
    const float* Wk    = (const float*)d_in[3];
    const float* Wv1   = (const float*)d_in[4];
    const float* ln_g  = (const float*)d_in[5];
    const float* ln_b  = (const float*)d_in[6];
    const float* Wconv = (const float*)d_in[7];
    const float* Wout  = (const float*)d_in[8];
    float* out = (float*)d_out;

    float *qp, *kp, *midp, *st, *simp, *wp, *opp, *pp, *rnd;
    cudaGetSymbolAddress((void**)&qp,   g_q);
    cudaGetSymbolAddress((void**)&kp,   g_k);
    cudaGetSymbolAddress((void**)&midp, g_mid);
    cudaGetSymbolAddress((void**)&st,   g_stats);
    cudaGetSymbolAddress((void**)&simp, g_sim);
    cudaGetSymbolAddress((void**)&wp,   g_w);
    cudaGetSymbolAddress((void**)&opp,  g_outpre);
    cudaGetSymbolAddress((void**)&pp,   g_part);
    cudaGetSymbolAddress((void**)&rnd,  g_rnd);
    float* x_r    = rnd;
    float* ctx_r  = x_r + (size_t)X4 * 4;
    float* Wq_r   = ctx_r + (size_t)CTX4 * 4;
    float* Wk_r   = Wq_r + (size_t)W4 * 4;
    float* Wv1_r  = Wk_r + (size_t)W4 * 4;
    float* Wout_r = Wv1_r + (size_t)WV14 * 4;

    const int SMEM = 3 * STG_BYTES;   // 98304
    cudaFuncSetAttribute(gemm_fused_tf32,  cudaFuncAttributeMaxDynamicSharedMemorySize, SMEM);
    cudaFuncSetAttribute(sim_lnstats_kernel, cudaFuncAttributeMaxDynamicSharedMemorySize, SMEM);
    cudaFuncSetAttribute(gemm_out_tf32,    cudaFuncAttributeMaxDynamicSharedMemorySize, SMEM);

    const int T = 256;
    auto blks = [](int n) { return (n + 255) / 256; };

    // pre-round all tf32-GEMM inputs (RNA)
    round_tf32_kernel<<<blks(TOT4), T>>>(x, ctx, Wq, Wk, Wv1, Wout, rnd);

    // ONE tf32 launch: mid + k + q (q/k epilogue-rounded for the sim GEMM)
    gemm_fused_tf32<<<TOT_TILES, T, SMEM>>>(ctx_r, Wv1_r, midp, Wk_r, kp,
                                            x_r, Wq_r, qp);

    // merged: sim GEMM (144 CTAs) + LN stats (2056 CTAs), one launch
    sim_lnstats_kernel<<<SIMLN_CTAS, T, SMEM>>>(qp, kp, simp, midp, st);

    // attention: softmax + LN folded into the rank contraction
    attn_w2_kernel<<<dim3(NQ_, B_), 384>>>(simp, midp, st, ln_g, ln_b, wp);

    convout_kernel<<<BQ_ROWS, 256>>>(wp, Wconv, opp);

    // final = outpre @ Wout^T, tf32, split-K=4
    gemm_out_tf32<<<dim3(D_ / 128, BQ_ROWS / 128, 4), T, SMEM>>>(opp, Wout_r, pp);
    reduce_k<4><<<blks(BQ_ROWS * D_ / 4), T>>>(pp, out, BQ_ROWS * D_ / 4);
}